// round 13
// baseline (speedup 1.0000x reference)
#include <cuda_runtime.h>
#include <cuda_fp16.h>
#include <cstdint>

#define BB   32
#define NN   16384
#define DD   128
#define IDM  64
#define NCLS 10

// ---------------------------------------------------------------------------
// Scratch (device globals — no allocation allowed)
// ---------------------------------------------------------------------------
__device__ float g_scores[BB * NN];
__device__ float g_u[BB * DD];
__device__ float g_C[BB];
__device__ float g_tau[BB];
__device__ float g_gbar[BB * DD];
__device__ __align__(16) unsigned long long g_wfrag[2048];
__device__ float g_M1[DD * DD];    // M1[k,m] = sum_p wq2[k,p] wqp[p,m]
__device__ float g_A2t[DD * DD];   // A2t[m,i] = sum_j wx2[i,j] wkp[j,m]
__device__ float g_v[DD];          // v[m] = sum_i bx2[i] wkp[i,m] + bkp[m]
__device__ float g_cq[DD];         // cq[m] = sum_p bq2[p] wqp[p,m] + bqp[m]

__device__ __forceinline__ float gelu_exact(float x) {
    return 0.5f * x * (1.0f + erff(x * 0.7071067811865475f));
}

// tanh-form gelu via MUFU.TANH: 0.5x(1+tanh(0.798x(1+0.0447x^2)))
__device__ __forceinline__ float gelu_fast(float x) {
    float y = 0.7978845608028654f * x * fmaf(0.044715f, x * x, 1.0f);
    float t;
    asm("tanh.approx.f32 %0, %1;" : "=f"(t) : "f"(y));
    float hx = 0.5f * x;
    return fmaf(hx, t, hx);
}

__device__ __forceinline__ void mma16816(float* c, const uint32_t* a,
                                         uint32_t b0, uint32_t b1) {
    asm volatile(
        "mma.sync.aligned.m16n8k16.row.col.f32.f16.f16.f32 "
        "{%0,%1,%2,%3}, {%4,%5,%6,%7}, {%8,%9}, {%0,%1,%2,%3};"
        : "+f"(c[0]), "+f"(c[1]), "+f"(c[2]), "+f"(c[3])
        : "r"(a[0]), "r"(a[1]), "r"(a[2]), "r"(a[3]), "r"(b0), "r"(b1));
}

__device__ __forceinline__ uint32_t pack_h2(float lo, float hi) {
    __half2 h = __floats2half2_rn(lo, hi);
    return *reinterpret_cast<uint32_t*>(&h);
}

// ---------------------------------------------------------------------------
// k1a: independent precomputes. 274 blocks x 128 threads.
// ---------------------------------------------------------------------------
__global__ void __launch_bounds__(128) k1a(
    const float* __restrict__ wx1,
    const float* __restrict__ wq2, const float* __restrict__ bq2,
    const float* __restrict__ wqp, const float* __restrict__ bqp,
    const float* __restrict__ wkp, const float* __restrict__ bkp,
    const float* __restrict__ wx2, const float* __restrict__ bx2)
{
    const int bid = blockIdx.x;
    const int t   = threadIdx.x;

    if (bid < 128) {                       // M1[k,m]
        const int k = bid;
        float a0 = 0.f, a1 = 0.f;
#pragma unroll 8
        for (int p = 0; p < DD; p += 2) {
            a0 += wq2[k * DD + p + 0] * wqp[(p + 0) * DD + t];
            a1 += wq2[k * DD + p + 1] * wqp[(p + 1) * DD + t];
        }
        g_M1[k * DD + t] = a0 + a1;
    } else if (bid < 256) {                // A2[i,m] stored transposed
        const int i = bid - 128;
        float a0 = 0.f, a1 = 0.f;
#pragma unroll 8
        for (int j = 0; j < DD; j += 2) {
            a0 += wx2[i * DD + j + 0] * wkp[(j + 0) * DD + t];
            a1 += wx2[i * DD + j + 1] * wkp[(j + 1) * DD + t];
        }
        g_A2t[t * DD + i] = a0 + a1;
    } else if (bid < 272) {                // fp16 weight fragments for k2
        int s = (bid - 256) * 128 + t;
        int l  = s & 31;
        int ks = (s >> 5) & 3;
        int nt = s >> 7;
        int n  = nt * 8 + (l >> 2);
        int k0 = ks * 16 + (l & 3) * 2;
        float w0 = wx1[(k0 + 0) * DD + n];
        float w1 = wx1[(k0 + 1) * DD + n];
        float w8 = wx1[(k0 + 8) * DD + n];
        float w9 = wx1[(k0 + 9) * DD + n];
        g_wfrag[s] = (unsigned long long)pack_h2(w0, w1)
                   | ((unsigned long long)pack_h2(w8, w9) << 32);
    } else if (bid == 272) {               // v[m]
        float a = 0.f;
#pragma unroll 8
        for (int i = 0; i < DD; i++) a += bx2[i] * wkp[i * DD + t];
        g_v[t] = a + bkp[t];
    } else {                               // cq[m]
        float a = 0.f;
#pragma unroll 8
        for (int p = 0; p < DD; p++) a += bq2[p] * wqp[p * DD + t];
        g_cq[t] = a + bqp[t];
    }
}

// ---------------------------------------------------------------------------
// k1c: per-batch finals. 32 blocks x 128.
// ---------------------------------------------------------------------------
__global__ void __launch_bounds__(128) k1c(
    const float* __restrict__ xq_all,
    const float* __restrict__ wq1, const float* __restrict__ bq1)
{
    __shared__ float sg[DD];
    __shared__ float qm[DD];
    __shared__ float red[4];
    const int b = blockIdx.x;
    const int t = threadIdx.x;

    sg[t] = gelu_exact(xq_all[b] * wq1[t] + bq1[t]);
    __syncthreads();

    {
        float a0 = 0.f, a1 = 0.f;
#pragma unroll 8
        for (int k = 0; k < DD; k += 2) {
            a0 += sg[k + 0] * g_M1[(k + 0) * DD + t];
            a1 += sg[k + 1] * g_M1[(k + 1) * DD + t];
        }
        qm[t] = a0 + a1 + g_cq[t];
    }
    __syncthreads();

    {
        float a0 = 0.f, a1 = 0.f;
#pragma unroll 8
        for (int m = 0; m < DD; m += 2) {
            a0 += g_A2t[(m + 0) * DD + t] * qm[m + 0];
            a1 += g_A2t[(m + 1) * DD + t] * qm[m + 1];
        }
        g_u[b * DD + t] = a0 + a1;
    }

    float p = qm[t] * g_v[t];
#pragma unroll
    for (int o = 16; o > 0; o >>= 1) p += __shfl_xor_sync(0xffffffffu, p, o);
    if ((t & 31) == 0) red[t >> 5] = p;
    __syncthreads();
    if (t == 0) g_C[b] = red[0] + red[1] + red[2] + red[3];
}

// ---------------------------------------------------------------------------
// Kernel 2 (dominant): single-product fp16 HMMA + MUFU.TANH gelu epilogue.
// Grid (NN/256, BB), 256 threads (8 warps).
// ---------------------------------------------------------------------------
static constexpr int S_B   = 0;         // 16384 bytes
static constexpr int S_US  = 16384;
static constexpr int S_BXS = S_US + 512;
static constexpr int S_TOT = S_BXS + 512;

__global__ void __launch_bounds__(256) k2_scores_hmma(
    const float* __restrict__ x_items,
    const float* __restrict__ bx1)
{
    extern __shared__ char smem[];
    const int tid = threadIdx.x;
    const int wid = tid >> 5;
    const int lid = tid & 31;
    const int qr  = lid >> 2;
    const int qc  = lid & 3;
    const int b   = blockIdx.y;
    const int tile0 = blockIdx.x * 256;

    float* us  = reinterpret_cast<float*>(smem + S_US);
    float* bxs = reinterpret_cast<float*>(smem + S_BXS);
    if (tid < DD) {
        us[tid]  = g_u[b * DD + tid];
        bxs[tid] = bx1[tid];
    }
    const float Cs = g_C[b];

    {
        const uint4* gf = reinterpret_cast<const uint4*>(g_wfrag);
        uint4* bs = reinterpret_cast<uint4*>(smem + S_B);
#pragma unroll
        for (int j = 0; j < 4; j++) bs[tid + j * 256] = gf[tid + j * 256];
    }

    uint32_t A[2][4][4];
    {
        const float* xb = x_items + ((size_t)b * NN + (size_t)tile0) * IDM;
#pragma unroll
        for (int mt = 0; mt < 2; mt++) {
            int r0 = wid * 32 + mt * 16 + qr;
#pragma unroll
            for (int ks = 0; ks < 4; ks++) {
                int k0 = ks * 16 + qc * 2;
                float2 v00 = *reinterpret_cast<const float2*>(xb + (size_t)r0 * IDM + k0);
                float2 v10 = *reinterpret_cast<const float2*>(xb + (size_t)(r0 + 8) * IDM + k0);
                float2 v01 = *reinterpret_cast<const float2*>(xb + (size_t)r0 * IDM + k0 + 8);
                float2 v11 = *reinterpret_cast<const float2*>(xb + (size_t)(r0 + 8) * IDM + k0 + 8);
                A[mt][ks][0] = pack_h2(v00.x, v00.y);
                A[mt][ks][1] = pack_h2(v10.x, v10.y);
                A[mt][ks][2] = pack_h2(v01.x, v01.y);
                A[mt][ks][3] = pack_h2(v11.x, v11.y);
            }
        }
    }
    __syncthreads();

    float sc[2][2] = {{0.f, 0.f}, {0.f, 0.f}};
#pragma unroll 1
    for (int nt = 0; nt < 16; nt++) {
        float c0[4] = {0.f, 0.f, 0.f, 0.f};
        float c1[4] = {0.f, 0.f, 0.f, 0.f};
#pragma unroll
        for (int ks = 0; ks < 4; ks++) {
            unsigned long long bb = *reinterpret_cast<const unsigned long long*>(
                smem + S_B + (((nt * 4 + ks) * 32) + lid) * 8);
            uint32_t b0 = (uint32_t)bb;
            uint32_t b1 = (uint32_t)(bb >> 32);
            mma16816(c0, A[0][ks], b0, b1);
            mma16816(c1, A[1][ks], b0, b1);
        }
        int n0 = nt * 8 + qc * 2;
        float2 bias = *reinterpret_cast<const float2*>(&bxs[n0]);
        float2 uu   = *reinterpret_cast<const float2*>(&us[n0]);
        sc[0][0] += gelu_fast(c0[0] + bias.x) * uu.x + gelu_fast(c0[1] + bias.y) * uu.y;
        sc[0][1] += gelu_fast(c0[2] + bias.x) * uu.x + gelu_fast(c0[3] + bias.y) * uu.y;
        sc[1][0] += gelu_fast(c1[0] + bias.x) * uu.x + gelu_fast(c1[1] + bias.y) * uu.y;
        sc[1][1] += gelu_fast(c1[2] + bias.x) * uu.x + gelu_fast(c1[3] + bias.y) * uu.y;
    }

#pragma unroll
    for (int mt = 0; mt < 2; mt++) {
#pragma unroll
        for (int h = 0; h < 2; h++) {
            float v = sc[mt][h];
            v += __shfl_xor_sync(0xffffffffu, v, 1);
            v += __shfl_xor_sync(0xffffffffu, v, 2);
            sc[mt][h] = v;
        }
    }
    if (qc == 0) {
#pragma unroll
        for (int mt = 0; mt < 2; mt++) {
#pragma unroll
            for (int h = 0; h < 2; h++) {
                int item = tile0 + wid * 32 + mt * 16 + h * 8 + qr;
                g_scores[b * NN + item] =
                    0.08838834764831845f * (sc[mt][h] + Cs);
            }
        }
    }
}

// ---------------------------------------------------------------------------
// k3a: tau via Michelot fixed point, atomic-free reduction, monotone early
// exit. 32 blocks x 1024. Also zeroes g_gbar.
// ---------------------------------------------------------------------------
#define MICH_ROUNDS 20

__global__ void __launch_bounds__(1024) k3a_tau()
{
    __shared__ float sS[2][32];
    __shared__ float sK[2][32];
    __shared__ float sM[32];

    const int tid  = threadIdx.x;
    const int b    = blockIdx.x;
    const int lane = tid & 31;
    const int wid  = tid >> 5;
    const float* sc = g_scores + b * NN;

    if (tid < DD) g_gbar[b * DD + tid] = 0.f;

    float z[16];
#pragma unroll
    for (int j = 0; j < 16; j++) z[j] = sc[tid + j * 1024];

    float m = z[0];
#pragma unroll
    for (int j = 1; j < 16; j++) m = fmaxf(m, z[j]);
#pragma unroll
    for (int o = 16; o > 0; o >>= 1) m = fmaxf(m, __shfl_xor_sync(0xffffffffu, m, o));
    if (lane == 0) sM[wid] = m;
    __syncthreads();
    float zmax = sM[0];
#pragma unroll
    for (int j = 1; j < 32; j++) zmax = fmaxf(zmax, sM[j]);

    // Michelot: tau_{r+1} = (sum_{z>tau_r} z - 1)/k ; monotone non-decreasing
    // from tau_0 = zmax - 1; fixed point = exact sparsemax threshold.
    float tau = zmax - 1.0f;
#pragma unroll 1
    for (int r = 0; r < MICH_ROUNDS; r++) {
        float s = 0.f, c = 0.f;
#pragma unroll
        for (int j = 0; j < 16; j++) {
            if (z[j] > tau) { s += z[j]; c += 1.f; }
        }
#pragma unroll
        for (int o = 16; o > 0; o >>= 1) {
            s += __shfl_xor_sync(0xffffffffu, s, o);
            c += __shfl_xor_sync(0xffffffffu, c, o);
        }
        const int p = r & 1;
        if (lane == 0) { sS[p][wid] = s; sK[p][wid] = c; }
        __syncthreads();
        float S = 0.f, K = 0.f;
#pragma unroll
        for (int j = 0; j < 32; j++) { S += sS[p][j]; K += sK[p][j]; }
        float tn = (S - 1.0f) / K;        // identical in all threads
        if (tn <= tau) break;             // monotone convergence => done
        tau = tn;
    }

    if (tid == 0) g_tau[b] = tau;
}

// ---------------------------------------------------------------------------
// k3b: chunk-parallel sparse accumulation. Grid (64, 32) x 256 threads.
// Each block: 256 items; each warp: one 32-item window.
// ---------------------------------------------------------------------------
__global__ void __launch_bounds__(256) k3b_accum(
    const float* __restrict__ x_items,
    const float* __restrict__ wx1, const float* __restrict__ bx1)
{
    __shared__ float accg[DD];
    const int tid  = threadIdx.x;
    const int lane = tid & 31;
    const int wid  = tid >> 5;
    const int b    = blockIdx.y;
    const int idx0 = blockIdx.x * 256 + wid * 32;

    if (tid < DD) accg[tid] = 0.f;
    __syncthreads();

    const float tau = g_tau[b];
    const float* sc = g_scores + b * NN;

    float zz = sc[idx0 + lane];
    unsigned msk = __ballot_sync(0xffffffffu, zz > tau);
    while (msk) {
        int jb = __ffs(msk) - 1;
        msk &= msk - 1;
        float w = __shfl_sync(0xffffffffu, zz, jb) - tau;
        int item = idx0 + jb;
        const float* xr = x_items + ((size_t)b * NN + (size_t)item) * IDM;
        float x0 = xr[2 * lane], x1 = xr[2 * lane + 1];
        float a0 = bx1[lane];
        float a1 = bx1[lane + 32];
        float a2 = bx1[lane + 64];
        float a3 = bx1[lane + 96];
#pragma unroll
        for (int k = 0; k < IDM; k++) {
            float xv = __shfl_sync(0xffffffffu, (k & 1) ? x1 : x0, k >> 1);
            a0 += xv * wx1[k * DD + lane];
            a1 += xv * wx1[k * DD + lane + 32];
            a2 += xv * wx1[k * DD + lane + 64];
            a3 += xv * wx1[k * DD + lane + 96];
        }
        atomicAdd(&accg[lane],      w * gelu_exact(a0));
        atomicAdd(&accg[lane + 32], w * gelu_exact(a1));
        atomicAdd(&accg[lane + 64], w * gelu_exact(a2));
        atomicAdd(&accg[lane + 96], w * gelu_exact(a3));
    }
    __syncthreads();
    if (tid < DD) {
        float v = accg[tid];
        if (v != 0.f) atomicAdd(&g_gbar[b * DD + tid], v);
    }
}

// ---------------------------------------------------------------------------
// k3c: head MLP. 32 blocks x 128 threads.
// ---------------------------------------------------------------------------
__global__ void __launch_bounds__(128) k3c_head(
    const float* __restrict__ wx2, const float* __restrict__ bx2,
    const float* __restrict__ wvp, const float* __restrict__ bvp,
    const float* __restrict__ wp1, const float* __restrict__ bp1,
    const float* __restrict__ wp2, const float* __restrict__ bp2,
    float* __restrict__ out)
{
    __shared__ float accg[DD];
    __shared__ float buf1[DD];
    __shared__ float buf2[DD];
    const int b   = blockIdx.x;
    const int tid = threadIdx.x;

    accg[tid] = g_gbar[b * DD + tid];
    __syncthreads();

    {
        float a0 = 0.f, a1 = 0.f, a2 = 0.f, a3 = 0.f;
#pragma unroll 8
        for (int k = 0; k < DD; k += 4) {
            a0 += accg[k + 0] * wx2[(k + 0) * DD + tid];
            a1 += accg[k + 1] * wx2[(k + 1) * DD + tid];
            a2 += accg[k + 2] * wx2[(k + 2) * DD + tid];
            a3 += accg[k + 3] * wx2[(k + 3) * DD + tid];
        }
        buf1[tid] = (a0 + a1) + (a2 + a3) + bx2[tid];
    }
    __syncthreads();
    {
        float a0 = 0.f, a1 = 0.f, a2 = 0.f, a3 = 0.f;
#pragma unroll 8
        for (int k = 0; k < DD; k += 4) {
            a0 += buf1[k + 0] * wvp[(k + 0) * DD + tid];
            a1 += buf1[k + 1] * wvp[(k + 1) * DD + tid];
            a2 += buf1[k + 2] * wvp[(k + 2) * DD + tid];
            a3 += buf1[k + 3] * wvp[(k + 3) * DD + tid];
        }
        buf2[tid] = (a0 + a1) + (a2 + a3) + bvp[tid];
    }
    __syncthreads();
    {
        float a0 = 0.f, a1 = 0.f, a2 = 0.f, a3 = 0.f;
#pragma unroll 8
        for (int k = 0; k < DD; k += 4) {
            a0 += buf2[k + 0] * wp1[(k + 0) * DD + tid];
            a1 += buf2[k + 1] * wp1[(k + 1) * DD + tid];
            a2 += buf2[k + 2] * wp1[(k + 2) * DD + tid];
            a3 += buf2[k + 3] * wp1[(k + 3) * DD + tid];
        }
        buf1[tid] = gelu_exact((a0 + a1) + (a2 + a3) + bp1[tid]);
    }
    __syncthreads();
    if (tid < NCLS) {
        float o = bp2[tid];
#pragma unroll 8
        for (int k = 0; k < DD; k++) o += buf1[k] * wp2[k * NCLS + tid];
        out[b * NCLS + tid] = o;
    }
}

// ---------------------------------------------------------------------------
extern "C" void kernel_launch(void* const* d_in, const int* in_sizes, int n_in,
                              void* d_out, int out_size)
{
    const float* x_items = (const float*)d_in[0];
    const float* x_query = (const float*)d_in[1];
    const float* wx1 = (const float*)d_in[2];
    const float* bx1 = (const float*)d_in[3];
    const float* wx2 = (const float*)d_in[4];
    const float* bx2 = (const float*)d_in[5];
    const float* wq1 = (const float*)d_in[6];
    const float* bq1 = (const float*)d_in[7];
    const float* wq2 = (const float*)d_in[8];
    const float* bq2 = (const float*)d_in[9];
    const float* wqp = (const float*)d_in[10];
    const float* bqp = (const float*)d_in[11];
    const float* wkp = (const float*)d_in[12];
    const float* bkp = (const float*)d_in[13];
    const float* wvp = (const float*)d_in[14];
    const float* bvp = (const float*)d_in[15];
    const float* wp1 = (const float*)d_in[16];
    const float* bp1 = (const float*)d_in[17];
    const float* wp2 = (const float*)d_in[18];
    const float* bp2 = (const float*)d_in[19];
    float* out = (float*)d_out;

    cudaFuncSetAttribute(k2_scores_hmma,
                         cudaFuncAttributeMaxDynamicSharedMemorySize, S_TOT);

    k1a<<<274, 128>>>(wx1, wq2, bq2, wqp, bqp, wkp, bkp, wx2, bx2);
    k1c<<<BB, 128>>>(x_query, wq1, bq1);

    dim3 g2(NN / 256, BB);
    k2_scores_hmma<<<g2, 256, S_TOT>>>(x_items, bx1);

    k3a_tau<<<BB, 1024>>>();
    dim3 g3(64, BB);
    k3b_accum<<<g3, 256>>>(x_items, wx1, bx1);
    k3c_head<<<BB, 128>>>(wx2, bx2, wvp, bvp, wp1, bp1, wp2, bp2, out);
}

// round 14
// speedup vs baseline: 1.0104x; 1.0104x over previous
#include <cuda_runtime.h>
#include <cuda_fp16.h>
#include <cstdint>

#define BB   32
#define NN   16384
#define DD   128
#define IDM  64
#define NCLS 10

// ---------------------------------------------------------------------------
// Scratch (device globals — no allocation allowed)
// ---------------------------------------------------------------------------
__device__ float g_scores[BB * NN];
__device__ float g_u[BB * DD];
__device__ float g_C[BB];
__device__ float g_tau[BB];
__device__ float g_gbar[BB * DD];
__device__ __align__(16) unsigned long long g_wfrag[2048];
__device__ float g_M1[DD * DD];    // M1[k,m] = sum_p wq2[k,p] wqp[p,m]
__device__ float g_A2t[DD * DD];   // A2t[m,i] = sum_j wx2[i,j] wkp[j,m]
__device__ float g_v[DD];          // v[m] = sum_i bx2[i] wkp[i,m] + bkp[m]
__device__ float g_cq[DD];         // cq[m] = sum_p bq2[p] wqp[p,m] + bqp[m]

__device__ __forceinline__ float gelu_exact(float x) {
    return 0.5f * x * (1.0f + erff(x * 0.7071067811865475f));
}

// score-dot term: gelu_tanh(x)*u = x*u*sigmoid(2y), y=0.798x(1+0.0447x^2)
// ys = -2*log2(e)*y  pre-fused:  ys = x * fma(-0.10294322, x^2, -2.30220798)
__device__ __forceinline__ float gdot(float x, float u) {
    float x2 = x * x;
    float ys = x * fmaf(-0.10294322f, x2, -2.30220798f);
    float e;
    asm("ex2.approx.f32 %0, %1;" : "=f"(e) : "f"(ys));
    float d = e + 1.0f;
    float r;
    asm("rcp.approx.f32 %0, %1;" : "=f"(r) : "f"(d));
    return (x * u) * r;
}

__device__ __forceinline__ void mma16816(float* c, const uint32_t* a,
                                         uint32_t b0, uint32_t b1) {
    asm volatile(
        "mma.sync.aligned.m16n8k16.row.col.f32.f16.f16.f32 "
        "{%0,%1,%2,%3}, {%4,%5,%6,%7}, {%8,%9}, {%0,%1,%2,%3};"
        : "+f"(c[0]), "+f"(c[1]), "+f"(c[2]), "+f"(c[3])
        : "r"(a[0]), "r"(a[1]), "r"(a[2]), "r"(a[3]), "r"(b0), "r"(b1));
}

__device__ __forceinline__ uint32_t pack_h2(float lo, float hi) {
    __half2 h = __floats2half2_rn(lo, hi);
    return *reinterpret_cast<uint32_t*>(&h);
}

// ---------------------------------------------------------------------------
// k1a: independent precomputes. 274 blocks x 128 threads.
// ---------------------------------------------------------------------------
__global__ void __launch_bounds__(128) k1a(
    const float* __restrict__ wx1,
    const float* __restrict__ wq2, const float* __restrict__ bq2,
    const float* __restrict__ wqp, const float* __restrict__ bqp,
    const float* __restrict__ wkp, const float* __restrict__ bkp,
    const float* __restrict__ wx2, const float* __restrict__ bx2)
{
    const int bid = blockIdx.x;
    const int t   = threadIdx.x;

    if (bid < 128) {                       // M1[k,m]
        const int k = bid;
        float a0 = 0.f, a1 = 0.f;
#pragma unroll 8
        for (int p = 0; p < DD; p += 2) {
            a0 += wq2[k * DD + p + 0] * wqp[(p + 0) * DD + t];
            a1 += wq2[k * DD + p + 1] * wqp[(p + 1) * DD + t];
        }
        g_M1[k * DD + t] = a0 + a1;
    } else if (bid < 256) {                // A2[i,m] stored transposed
        const int i = bid - 128;
        float a0 = 0.f, a1 = 0.f;
#pragma unroll 8
        for (int j = 0; j < DD; j += 2) {
            a0 += wx2[i * DD + j + 0] * wkp[(j + 0) * DD + t];
            a1 += wx2[i * DD + j + 1] * wkp[(j + 1) * DD + t];
        }
        g_A2t[t * DD + i] = a0 + a1;
    } else if (bid < 272) {                // fp16 weight fragments for k2
        int s = (bid - 256) * 128 + t;
        int l  = s & 31;
        int ks = (s >> 5) & 3;
        int nt = s >> 7;
        int n  = nt * 8 + (l >> 2);
        int k0 = ks * 16 + (l & 3) * 2;
        float w0 = wx1[(k0 + 0) * DD + n];
        float w1 = wx1[(k0 + 1) * DD + n];
        float w8 = wx1[(k0 + 8) * DD + n];
        float w9 = wx1[(k0 + 9) * DD + n];
        g_wfrag[s] = (unsigned long long)pack_h2(w0, w1)
                   | ((unsigned long long)pack_h2(w8, w9) << 32);
    } else if (bid == 272) {               // v[m]
        float a = 0.f;
#pragma unroll 8
        for (int i = 0; i < DD; i++) a += bx2[i] * wkp[i * DD + t];
        g_v[t] = a + bkp[t];
    } else {                               // cq[m]
        float a = 0.f;
#pragma unroll 8
        for (int p = 0; p < DD; p++) a += bq2[p] * wqp[p * DD + t];
        g_cq[t] = a + bqp[t];
    }
}

// ---------------------------------------------------------------------------
// k1c: per-batch finals. 32 blocks x 128.
// ---------------------------------------------------------------------------
__global__ void __launch_bounds__(128) k1c(
    const float* __restrict__ xq_all,
    const float* __restrict__ wq1, const float* __restrict__ bq1)
{
    __shared__ float sg[DD];
    __shared__ float qm[DD];
    __shared__ float red[4];
    const int b = blockIdx.x;
    const int t = threadIdx.x;

    sg[t] = gelu_exact(xq_all[b] * wq1[t] + bq1[t]);
    __syncthreads();

    {
        float a0 = 0.f, a1 = 0.f;
#pragma unroll 8
        for (int k = 0; k < DD; k += 2) {
            a0 += sg[k + 0] * g_M1[(k + 0) * DD + t];
            a1 += sg[k + 1] * g_M1[(k + 1) * DD + t];
        }
        qm[t] = a0 + a1 + g_cq[t];
    }
    __syncthreads();

    {
        float a0 = 0.f, a1 = 0.f;
#pragma unroll 8
        for (int m = 0; m < DD; m += 2) {
            a0 += g_A2t[(m + 0) * DD + t] * qm[m + 0];
            a1 += g_A2t[(m + 1) * DD + t] * qm[m + 1];
        }
        g_u[b * DD + t] = a0 + a1;
    }

    float p = qm[t] * g_v[t];
#pragma unroll
    for (int o = 16; o > 0; o >>= 1) p += __shfl_xor_sync(0xffffffffu, p, o);
    if ((t & 31) == 0) red[t >> 5] = p;
    __syncthreads();
    if (t == 0) g_C[b] = red[0] + red[1] + red[2] + red[3];
}

// ---------------------------------------------------------------------------
// Kernel 2 (dominant): single-product fp16 HMMA.
// Epilogue: bias seeded into accumulators; gelu*u via ex2+rcp (2 MUFU, 6 ALU).
// Grid (NN/256, BB), 256 threads (8 warps).
// ---------------------------------------------------------------------------
static constexpr int S_B   = 0;         // 16384 bytes
static constexpr int S_US  = 16384;
static constexpr int S_BXS = S_US + 512;
static constexpr int S_TOT = S_BXS + 512;

__global__ void __launch_bounds__(256) k2_scores_hmma(
    const float* __restrict__ x_items,
    const float* __restrict__ bx1)
{
    extern __shared__ char smem[];
    const int tid = threadIdx.x;
    const int wid = tid >> 5;
    const int lid = tid & 31;
    const int qr  = lid >> 2;
    const int qc  = lid & 3;
    const int b   = blockIdx.y;
    const int tile0 = blockIdx.x * 256;

    float* us  = reinterpret_cast<float*>(smem + S_US);
    float* bxs = reinterpret_cast<float*>(smem + S_BXS);
    if (tid < DD) {
        us[tid]  = g_u[b * DD + tid];
        bxs[tid] = bx1[tid];
    }
    const float Cs = g_C[b];

    {
        const uint4* gf = reinterpret_cast<const uint4*>(g_wfrag);
        uint4* bs = reinterpret_cast<uint4*>(smem + S_B);
#pragma unroll
        for (int j = 0; j < 4; j++) bs[tid + j * 256] = gf[tid + j * 256];
    }

    uint32_t A[2][4][4];
    {
        const float* xb = x_items + ((size_t)b * NN + (size_t)tile0) * IDM;
#pragma unroll
        for (int mt = 0; mt < 2; mt++) {
            int r0 = wid * 32 + mt * 16 + qr;
#pragma unroll
            for (int ks = 0; ks < 4; ks++) {
                int k0 = ks * 16 + qc * 2;
                float2 v00 = *reinterpret_cast<const float2*>(xb + (size_t)r0 * IDM + k0);
                float2 v10 = *reinterpret_cast<const float2*>(xb + (size_t)(r0 + 8) * IDM + k0);
                float2 v01 = *reinterpret_cast<const float2*>(xb + (size_t)r0 * IDM + k0 + 8);
                float2 v11 = *reinterpret_cast<const float2*>(xb + (size_t)(r0 + 8) * IDM + k0 + 8);
                A[mt][ks][0] = pack_h2(v00.x, v00.y);
                A[mt][ks][1] = pack_h2(v10.x, v10.y);
                A[mt][ks][2] = pack_h2(v01.x, v01.y);
                A[mt][ks][3] = pack_h2(v11.x, v11.y);
            }
        }
    }
    __syncthreads();

    float sc[2][2] = {{0.f, 0.f}, {0.f, 0.f}};
#pragma unroll 1
    for (int nt = 0; nt < 16; nt++) {
        int n0 = nt * 8 + qc * 2;
        float2 bias = *reinterpret_cast<const float2*>(&bxs[n0]);
        float2 uu   = *reinterpret_cast<const float2*>(&us[n0]);
        float c0[4] = {bias.x, bias.y, bias.x, bias.y};   // bias pre-seeded
        float c1[4] = {bias.x, bias.y, bias.x, bias.y};
#pragma unroll
        for (int ks = 0; ks < 4; ks++) {
            unsigned long long bb = *reinterpret_cast<const unsigned long long*>(
                smem + S_B + (((nt * 4 + ks) * 32) + lid) * 8);
            uint32_t b0 = (uint32_t)bb;
            uint32_t b1 = (uint32_t)(bb >> 32);
            mma16816(c0, A[0][ks], b0, b1);
            mma16816(c1, A[1][ks], b0, b1);
        }
        sc[0][0] += gdot(c0[0], uu.x) + gdot(c0[1], uu.y);
        sc[0][1] += gdot(c0[2], uu.x) + gdot(c0[3], uu.y);
        sc[1][0] += gdot(c1[0], uu.x) + gdot(c1[1], uu.y);
        sc[1][1] += gdot(c1[2], uu.x) + gdot(c1[3], uu.y);
    }

#pragma unroll
    for (int mt = 0; mt < 2; mt++) {
#pragma unroll
        for (int h = 0; h < 2; h++) {
            float v = sc[mt][h];
            v += __shfl_xor_sync(0xffffffffu, v, 1);
            v += __shfl_xor_sync(0xffffffffu, v, 2);
            sc[mt][h] = v;
        }
    }
    if (qc == 0) {
#pragma unroll
        for (int mt = 0; mt < 2; mt++) {
#pragma unroll
            for (int h = 0; h < 2; h++) {
                int item = tile0 + wid * 32 + mt * 16 + h * 8 + qr;
                g_scores[b * NN + item] =
                    0.08838834764831845f * (sc[mt][h] + Cs);
            }
        }
    }
}

// ---------------------------------------------------------------------------
// k3a: Michelot fixed point; cheap per-round reduction (warp0 reduces the 32
// slots via shfl, scalar broadcast). 32 blocks x 1024. Also zeroes g_gbar.
// ---------------------------------------------------------------------------
#define MICH_ROUNDS 20

__global__ void __launch_bounds__(1024) k3a_tau()
{
    __shared__ float sS[32];
    __shared__ float sK[32];
    __shared__ float sM[32];
    __shared__ float bc[1];

    const int tid  = threadIdx.x;
    const int b    = blockIdx.x;
    const int lane = tid & 31;
    const int wid  = tid >> 5;
    const float* sc = g_scores + b * NN;

    if (tid < DD) g_gbar[b * DD + tid] = 0.f;

    float z[16];
#pragma unroll
    for (int j = 0; j < 16; j++) z[j] = sc[tid + j * 1024];

    // block max (warp -> slot -> warp0 -> broadcast)
    float m = z[0];
#pragma unroll
    for (int j = 1; j < 16; j++) m = fmaxf(m, z[j]);
#pragma unroll
    for (int o = 16; o > 0; o >>= 1) m = fmaxf(m, __shfl_xor_sync(0xffffffffu, m, o));
    if (lane == 0) sM[wid] = m;
    __syncthreads();
    if (wid == 0) {
        float v = sM[lane];
#pragma unroll
        for (int o = 16; o > 0; o >>= 1) v = fmaxf(v, __shfl_xor_sync(0xffffffffu, v, o));
        if (lane == 0) bc[0] = v;
    }
    __syncthreads();
    const float zmax = bc[0];

    // Michelot: tau_{r+1} = (sum_{z>tau_r} z - 1)/k ; monotone non-decreasing.
    float tau = zmax - 1.0f;
#pragma unroll 1
    for (int r = 0; r < MICH_ROUNDS; r++) {
        float s = 0.f, c = 0.f;
#pragma unroll
        for (int j = 0; j < 16; j++) {
            if (z[j] > tau) { s += z[j]; c += 1.f; }
        }
#pragma unroll
        for (int o = 16; o > 0; o >>= 1) {
            s += __shfl_xor_sync(0xffffffffu, s, o);
            c += __shfl_xor_sync(0xffffffffu, c, o);
        }
        if (lane == 0) { sS[wid] = s; sK[wid] = c; }
        __syncthreads();
        if (wid == 0) {
            float s2 = sS[lane], c2 = sK[lane];
#pragma unroll
            for (int o = 16; o > 0; o >>= 1) {
                s2 += __shfl_xor_sync(0xffffffffu, s2, o);
                c2 += __shfl_xor_sync(0xffffffffu, c2, o);
            }
            if (lane == 0) bc[0] = (s2 - 1.0f) / c2;
        }
        __syncthreads();
        float tn = bc[0];                 // identical in all threads
        if (tn <= tau) break;             // monotone convergence => done
        tau = tn;
    }

    if (tid == 0) g_tau[b] = tau;
}

// ---------------------------------------------------------------------------
// k3b: chunk-parallel sparse accumulation. Grid (32, 32) x 256 threads.
// Each block: 512 items; each warp: 2 windows of 32.
// ---------------------------------------------------------------------------
__global__ void __launch_bounds__(256) k3b_accum(
    const float* __restrict__ x_items,
    const float* __restrict__ wx1, const float* __restrict__ bx1)
{
    __shared__ float accg[DD];
    const int tid  = threadIdx.x;
    const int lane = tid & 31;
    const int wid  = tid >> 5;
    const int b    = blockIdx.y;
    const int base = blockIdx.x * 512 + wid * 64;

    if (tid < DD) accg[tid] = 0.f;
    __syncthreads();

    const float tau = g_tau[b];
    const float* sc = g_scores + b * NN;

#pragma unroll 1
    for (int win = 0; win < 2; win++) {
        int idx0 = base + win * 32;
        float zz = sc[idx0 + lane];
        unsigned msk = __ballot_sync(0xffffffffu, zz > tau);
        while (msk) {
            int jb = __ffs(msk) - 1;
            msk &= msk - 1;
            float w = __shfl_sync(0xffffffffu, zz, jb) - tau;
            int item = idx0 + jb;
            const float* xr = x_items + ((size_t)b * NN + (size_t)item) * IDM;
            float x0 = xr[2 * lane], x1 = xr[2 * lane + 1];
            float a0 = bx1[lane];
            float a1 = bx1[lane + 32];
            float a2 = bx1[lane + 64];
            float a3 = bx1[lane + 96];
#pragma unroll
            for (int k = 0; k < IDM; k++) {
                float xv = __shfl_sync(0xffffffffu, (k & 1) ? x1 : x0, k >> 1);
                a0 += xv * wx1[k * DD + lane];
                a1 += xv * wx1[k * DD + lane + 32];
                a2 += xv * wx1[k * DD + lane + 64];
                a3 += xv * wx1[k * DD + lane + 96];
            }
            atomicAdd(&accg[lane],      w * gelu_exact(a0));
            atomicAdd(&accg[lane + 32], w * gelu_exact(a1));
            atomicAdd(&accg[lane + 64], w * gelu_exact(a2));
            atomicAdd(&accg[lane + 96], w * gelu_exact(a3));
        }
    }
    __syncthreads();
    if (tid < DD) {
        float v = accg[tid];
        if (v != 0.f) atomicAdd(&g_gbar[b * DD + tid], v);
    }
}

// ---------------------------------------------------------------------------
// k3c: head MLP. 32 blocks x 128 threads.
// ---------------------------------------------------------------------------
__global__ void __launch_bounds__(128) k3c_head(
    const float* __restrict__ wx2, const float* __restrict__ bx2,
    const float* __restrict__ wvp, const float* __restrict__ bvp,
    const float* __restrict__ wp1, const float* __restrict__ bp1,
    const float* __restrict__ wp2, const float* __restrict__ bp2,
    float* __restrict__ out)
{
    __shared__ float accg[DD];
    __shared__ float buf1[DD];
    __shared__ float buf2[DD];
    const int b   = blockIdx.x;
    const int tid = threadIdx.x;

    accg[tid] = g_gbar[b * DD + tid];
    __syncthreads();

    {
        float a0 = 0.f, a1 = 0.f, a2 = 0.f, a3 = 0.f;
#pragma unroll 8
        for (int k = 0; k < DD; k += 4) {
            a0 += accg[k + 0] * wx2[(k + 0) * DD + tid];
            a1 += accg[k + 1] * wx2[(k + 1) * DD + tid];
            a2 += accg[k + 2] * wx2[(k + 2) * DD + tid];
            a3 += accg[k + 3] * wx2[(k + 3) * DD + tid];
        }
        buf1[tid] = (a0 + a1) + (a2 + a3) + bx2[tid];
    }
    __syncthreads();
    {
        float a0 = 0.f, a1 = 0.f, a2 = 0.f, a3 = 0.f;
#pragma unroll 8
        for (int k = 0; k < DD; k += 4) {
            a0 += buf1[k + 0] * wvp[(k + 0) * DD + tid];
            a1 += buf1[k + 1] * wvp[(k + 1) * DD + tid];
            a2 += buf1[k + 2] * wvp[(k + 2) * DD + tid];
            a3 += buf1[k + 3] * wvp[(k + 3) * DD + tid];
        }
        buf2[tid] = (a0 + a1) + (a2 + a3) + bvp[tid];
    }
    __syncthreads();
    {
        float a0 = 0.f, a1 = 0.f, a2 = 0.f, a3 = 0.f;
#pragma unroll 8
        for (int k = 0; k < DD; k += 4) {
            a0 += buf2[k + 0] * wp1[(k + 0) * DD + tid];
            a1 += buf2[k + 1] * wp1[(k + 1) * DD + tid];
            a2 += buf2[k + 2] * wp1[(k + 2) * DD + tid];
            a3 += buf2[k + 3] * wp1[(k + 3) * DD + tid];
        }
        buf1[tid] = gelu_exact((a0 + a1) + (a2 + a3) + bp1[tid]);
    }
    __syncthreads();
    if (tid < NCLS) {
        float o = bp2[tid];
#pragma unroll 8
        for (int k = 0; k < DD; k++) o += buf1[k] * wp2[k * NCLS + tid];
        out[b * NCLS + tid] = o;
    }
}

// ---------------------------------------------------------------------------
extern "C" void kernel_launch(void* const* d_in, const int* in_sizes, int n_in,
                              void* d_out, int out_size)
{
    const float* x_items = (const float*)d_in[0];
    const float* x_query = (const float*)d_in[1];
    const float* wx1 = (const float*)d_in[2];
    const float* bx1 = (const float*)d_in[3];
    const float* wx2 = (const float*)d_in[4];
    const float* bx2 = (const float*)d_in[5];
    const float* wq1 = (const float*)d_in[6];
    const float* bq1 = (const float*)d_in[7];
    const float* wq2 = (const float*)d_in[8];
    const float* bq2 = (const float*)d_in[9];
    const float* wqp = (const float*)d_in[10];
    const float* bqp = (const float*)d_in[11];
    const float* wkp = (const float*)d_in[12];
    const float* bkp = (const float*)d_in[13];
    const float* wvp = (const float*)d_in[14];
    const float* bvp = (const float*)d_in[15];
    const float* wp1 = (const float*)d_in[16];
    const float* bp1 = (const float*)d_in[17];
    const float* wp2 = (const float*)d_in[18];
    const float* bp2 = (const float*)d_in[19];
    float* out = (float*)d_out;

    cudaFuncSetAttribute(k2_scores_hmma,
                         cudaFuncAttributeMaxDynamicSharedMemorySize, S_TOT);

    k1a<<<274, 128>>>(wx1, wq2, bq2, wqp, bqp, wkp, bkp, wx2, bx2);
    k1c<<<BB, 128>>>(x_query, wq1, bq1);

    dim3 g2(NN / 256, BB);
    k2_scores_hmma<<<g2, 256, S_TOT>>>(x_items, bx1);

    k3a_tau<<<BB, 1024>>>();
    dim3 g3(32, BB);
    k3b_accum<<<g3, 256>>>(x_items, wx1, bx1);
    k3c_head<<<BB, 128>>>(wx2, bx2, wvp, bvp, wp1, bp1, wp2, bp2, out);
}